// round 2
// baseline (speedup 1.0000x reference)
#include <cuda_runtime.h>

// LMNN loss on GB300 — single-wave version.
// outputs: [2048, 512, 128] f32, label_inds: [2048, 511] i32, out: scalar f32.
//
// One CTA per segment, 128 threads (4 warps), 16 CTAs/SM -> all 2048 CTAs
// resident in ONE wave (2432 slots on 152 SMs), eliminating the 1.68-wave
// tail that capped DRAM at 79%.
// Warp-per-point: lane l holds float4 of dims [4l,4l+4) -> each 512B point
// row is one coalesced LDG.128 per lane.

#define NSEG 2048
#define PPS  512
#define DDIM 128
#define NPTS 511   // PPS - 1
#define NTHR 128
#define NWRP 4

__global__ void lmnn_init_out(float* out) { *out = 0.0f; }

__global__ __launch_bounds__(NTHR, 16)
void lmnn_kernel(const float* __restrict__ outputs,
                 const int*   __restrict__ labels,
                 float*       __restrict__ out)
{
    __shared__ float sh_d2[NPTS];
    __shared__ int   sh_same[NPTS];
    __shared__ float sh_red[NWRP];

    const int seg  = blockIdx.x;
    const int tid  = threadIdx.x;
    const int warp = tid >> 5;
    const int lane = tid & 31;

    const float4* base = reinterpret_cast<const float4*>(
        outputs + (size_t)seg * PPS * DDIM);

    // Center row: lane l owns dims [4l, 4l+4). Redundant per warp; L1/L2 hit.
    const float4 c = base[lane];

    // Same-label flags vs label of first point. Coalesced int loads.
    const int* lab = labels + (size_t)seg * NPTS;
    const int lab0 = lab[0];
    for (int j = tid; j < NPTS; j += NTHR)
        sh_same[j] = (lab[j] == lab0);

    // d2 per point: warp w handles points w, w+4, w+8, ...  (~128 per warp).
    // unroll 4 -> 4 independent LDG.128 in flight per warp before the
    // dependent shuffle chains.
    #pragma unroll 4
    for (int j = warp; j < NPTS; j += NWRP) {
        const float4 p = base[(j + 1) * (DDIM / 4) + lane];
        const float dx = p.x - c.x;
        const float dy = p.y - c.y;
        const float dz = p.z - c.z;
        const float dw = p.w - c.w;
        float s = dx * dx + dy * dy + dz * dz + dw * dw;
        #pragma unroll
        for (int o = 16; o > 0; o >>= 1)
            s += __shfl_xor_sync(0xffffffffu, s, o);
        if (lane == 0) sh_d2[j] = s;
    }
    __syncthreads();

    // pull_d = min d2 over same-label points (j=0 is always same-label).
    float lmin = __int_as_float(0x7f800000);  // +inf
    for (int j = tid; j < NPTS; j += NTHR)
        if (sh_same[j]) lmin = fminf(lmin, sh_d2[j]);
    #pragma unroll
    for (int o = 16; o > 0; o >>= 1)
        lmin = fminf(lmin, __shfl_xor_sync(0xffffffffu, lmin, o));
    if (lane == 0) sh_red[warp] = lmin;
    __syncthreads();

    float pull = sh_red[0];
    #pragma unroll
    for (int w = 1; w < NWRP; w++) pull = fminf(pull, sh_red[w]);
    const float margin = 1.0f + pull;

    // push = sum over diff-label points of max(margin - d2, 0).
    float lsum = 0.0f;
    for (int j = tid; j < NPTS; j += NTHR)
        if (!sh_same[j]) lsum += fmaxf(margin - sh_d2[j], 0.0f);
    #pragma unroll
    for (int o = 16; o > 0; o >>= 1)
        lsum += __shfl_xor_sync(0xffffffffu, lsum, o);
    __syncthreads();          // all reads of sh_red (pull) done before reuse
    if (lane == 0) sh_red[warp] = lsum;
    __syncthreads();

    if (tid == 0) {
        float push = 0.0f;
        #pragma unroll
        for (int w = 0; w < NWRP; w++) push += sh_red[w];
        const float inv_n = 1.0f / (float)((size_t)NSEG * PPS);
        atomicAdd(out, (pull + push) * inv_n);
    }
}

extern "C" void kernel_launch(void* const* d_in, const int* in_sizes, int n_in,
                              void* d_out, int out_size)
{
    const float* outputs = (const float*)d_in[0];
    const int*   labels  = (const int*)d_in[1];
    float*       out     = (float*)d_out;

    lmnn_init_out<<<1, 1>>>(out);
    lmnn_kernel<<<NSEG, NTHR>>>(outputs, labels, out);
}